// round 14
// baseline (speedup 1.0000x reference)
#include <cuda_runtime.h>
#include <cuda_fp16.h>
#include <mma.h>
#include <cstdint>

using namespace nvcuda;

#define MAX_N 50000
#define MAX_E 800000
#define D_NODE 192
#define D_EDGE 64
#define D_IN 256
#define D_OUT 256

// ---------------- scratch (device globals: no allocations allowed) ----------
__device__ __half g_wh[D_IN * D_OUT];            // fp16 W [k][n]
__device__ __half g_fh[(size_t)MAX_N * D_NODE];  // fp16 outscale-prefolded feat
__device__ int   g_outdeg[MAX_N];
__device__ int   g_indeg[MAX_N];
__device__ int   g_starts[MAX_N];
__device__ int   g_cursor[MAX_N];
__device__ int2  g_bpair[MAX_E];    // (edge id, src node) per slot
__device__ float g_outscale[MAX_N];
__device__ float g_inscale[MAX_N];
__device__ int   g_total;

// ---------------- K1: zero counters ----------------------------------------
__global__ void zero_kernel(int N) {
    int i = blockIdx.x * blockDim.x + threadIdx.x;
    if (i < N) {
        g_outdeg[i] = 0;
        g_indeg[i]  = 0;
    }
    if (i == 0) g_total = 0;
}

// ---------------- K2: degree histograms -------------------------------------
__global__ void degree_kernel(const int* __restrict__ src,
                              const int* __restrict__ dst, int E) {
    int e = blockIdx.x * blockDim.x + threadIdx.x;
    if (e < E) {
        atomicAdd(&g_outdeg[src[e]], 1);
        atomicAdd(&g_indeg[dst[e]], 1);
    }
}

// ---------------- K3: per-node range allocation + scales ---------------------
__global__ void offsets_kernel(int N) {
    int i = blockIdx.x * blockDim.x + threadIdx.x;
    int lane = threadIdx.x & 31;
    int v = (i < N) ? g_indeg[i] : 0;
    if (i < N) {
        g_inscale[i]  = rsqrtf(fmaxf((float)v, 1.0f));
        g_outscale[i] = rsqrtf(fmaxf((float)g_outdeg[i], 1.0f));
    }
    int incl = v;
#pragma unroll
    for (int off = 1; off < 32; off <<= 1) {
        int x = __shfl_up_sync(0xffffffffu, incl, off);
        if (lane >= off) incl += x;
    }
    int warp_sum = __shfl_sync(0xffffffffu, incl, 31);
    int base = 0;
    if (lane == 31) base = atomicAdd(&g_total, warp_sum);
    base = __shfl_sync(0xffffffffu, base, 31);
    if (i < N) {
        int st = base + incl - v;
        g_starts[i] = st;
        g_cursor[i] = st;
    }
}

// ---------------- K4: bucket fill (counting sort by dst) --------------------
__global__ void bucket_kernel(const int* __restrict__ src,
                              const int* __restrict__ dst, int E) {
    int e = blockIdx.x * blockDim.x + threadIdx.x;
    if (e < E) {
        int d = dst[e];
        int pos = atomicAdd(&g_cursor[d], 1);
        g_bpair[pos] = make_int2(e, src[e]);
    }
}

// ---------------- K4b: W -> fp16 --------------------------------------------
__global__ void wsplit_kernel(const float* __restrict__ W) {
    int i = blockIdx.x * blockDim.x + threadIdx.x;
    if (i < D_IN * D_OUT) g_wh[i] = __float2half_rn(W[i]);
}

// ---------------- K4c: feat -> fp16, outscale pre-folded ---------------------
// g_fh[s][k] = half(outscale[s] * feat[s][k]); runs after offsets_kernel.
__global__ void fconv_kernel(const float* __restrict__ feat, int N) {
    int i = blockIdx.x * blockDim.x + threadIdx.x;     // one float4 per thread
    int total = N * (D_NODE / 4);
    if (i >= total) return;
    int row = i / (D_NODE / 4);
    float s = g_outscale[row];
    float4 v = __ldg(&((const float4*)feat)[i]);
    __half2 a = __floats2half2_rn(v.x * s, v.y * s);
    __half2 b = __floats2half2_rn(v.z * s, v.w * s);
    ((uint2*)g_fh)[i] = make_uint2(*(uint32_t*)&a, *(uint32_t*)&b);
}

// ---------------- K5: FUSED gather + GEMM ------------------------------------
// One CTA = 64 nodes x full N=256, 256 threads = 8 warps, 2 CTAs/SM
// (phase overlap across co-resident CTAs).
// Gather lane roles: lane l owns output cols 8l..8l+7.
//   lanes 0..23 : one uint4 of prefolded fp16 feat (cols 0..191)
//   lanes 24..31: two float4 of fp32 edge_feat   (cols 192..255)
// Phase 2: split-fp16 2-pass wmma GEMM: out = (Ah+Al) @ Bh + bias.
#define APAD 264
#define BPAD 264
#define A_BYTES  (64 * APAD * 2)               // 33792 per array
#define B_BYTES  (32 * BPAD * 2)               // 16896
#define FUSED_SMEM (2 * A_BYTES + B_BYTES)     // 84480

__global__ __launch_bounds__(256, 2) void fused_kernel(const float* __restrict__ edge_feat,
                                                       const float* __restrict__ bias,
                                                       float* __restrict__ out,
                                                       int N) {
    extern __shared__ __align__(16) unsigned char smem[];
    __half* sAh = (__half*)smem;
    __half* sAl = (__half*)(smem + A_BYTES);
    __half* sBh = (__half*)(smem + 2 * A_BYTES);
    float* sBias = (float*)sBh;                // overlay: 16*BPAD*4 == B_BYTES

    int t = threadIdx.x;
    int warpId = t >> 5, lane = t & 31;
    int m0 = blockIdx.x * 64;
    bool is_edge_lane = (lane >= 24);
    int q2 = (lane - 24) * 2;                  // edge float4 index (lanes 24..31)

    // ---------------- phase 1: gather 8 nodes per warp, unroll x4 -----------
#pragma unroll 1
    for (int j = 0; j < 8; j++) {
        int r = warpId * 8 + j;
        int node = m0 + r;
        int beg = 0, cnt = 0;
        if (node < N) { beg = g_starts[node]; cnt = g_indeg[node]; }

        float acc[8];
#pragma unroll
        for (int k = 0; k < 8; k++) acc[k] = 0.f;

        int i = 0;
        for (; i + 3 < cnt; i += 4) {
            int2 pr[4];
#pragma unroll
            for (int u = 0; u < 4; u++) pr[u] = g_bpair[beg + i + u];
            if (!is_edge_lane) {
                uint4 fv[4];
#pragma unroll
                for (int u = 0; u < 4; u++)
                    fv[u] = __ldg(&((const uint4*)(g_fh + (size_t)pr[u].y * D_NODE))[lane]);
#pragma unroll
                for (int u = 0; u < 4; u++) {
                    __half2* hp = (__half2*)&fv[u];
#pragma unroll
                    for (int k = 0; k < 4; k++) {
                        float2 f = __half22float2(hp[k]);
                        acc[2 * k]     += f.x;
                        acc[2 * k + 1] += f.y;
                    }
                }
            } else {
                float4 b0[4], b1[4];
#pragma unroll
                for (int u = 0; u < 4; u++) {
                    const float4* er = (const float4*)(edge_feat + (size_t)pr[u].x * D_EDGE);
                    b0[u] = __ldg(&er[q2]);
                    b1[u] = __ldg(&er[q2 + 1]);
                }
#pragma unroll
                for (int u = 0; u < 4; u++) {
                    acc[0] += b0[u].x; acc[1] += b0[u].y;
                    acc[2] += b0[u].z; acc[3] += b0[u].w;
                    acc[4] += b1[u].x; acc[5] += b1[u].y;
                    acc[6] += b1[u].z; acc[7] += b1[u].w;
                }
            }
        }
        for (; i < cnt; i++) {
            int2 pp = g_bpair[beg + i];
            if (!is_edge_lane) {
                uint4 fv = __ldg(&((const uint4*)(g_fh + (size_t)pp.y * D_NODE))[lane]);
                __half2* hp = (__half2*)&fv;
#pragma unroll
                for (int k = 0; k < 4; k++) {
                    float2 f = __half22float2(hp[k]);
                    acc[2 * k]     += f.x;
                    acc[2 * k + 1] += f.y;
                }
            } else {
                const float4* er = (const float4*)(edge_feat + (size_t)pp.x * D_EDGE);
                float4 b0 = __ldg(&er[q2]);
                float4 b1 = __ldg(&er[q2 + 1]);
                acc[0] += b0.x; acc[1] += b0.y; acc[2] += b0.z; acc[3] += b0.w;
                acc[4] += b1.x; acc[5] += b1.y; acc[6] += b1.z; acc[7] += b1.w;
            }
        }

        float is = (node < N) ? g_inscale[node] : 0.f;
#pragma unroll
        for (int k = 0; k < 8; k++) acc[k] *= is;

        // fp16 hi/lo split; lane owns cols 8*lane..8*lane+7
        __half hh[8], ll[8];
#pragma unroll
        for (int k = 0; k < 8; k++) {
            hh[k] = __float2half_rn(acc[k]);
            ll[k] = __float2half_rn(acc[k] - __half2float(hh[k]));
        }
        int base = r * APAD + 8 * lane;
        *(uint4*)(sAh + base) = *(uint4*)hh;
        *(uint4*)(sAl + base) = *(uint4*)ll;
    }

    // bias tile, replicated over 16 rows (accumulator-fragment init source)
#pragma unroll
    for (int u = 0; u < 16; u++) {
        int p = t + 256 * u;                    // 0..4095
        int row = p >> 8, col = p & 255;
        sBias[row * BPAD + col] = __ldg(&bias[col]);
    }
    __syncthreads();

    // ---------------- phase 2: GEMM (64x256 tile, 8 warps = 2M x 4N) --------
    int wm = warpId & 1;        // 2 positions x 32 rows
    int wn = warpId >> 1;       // 4 positions x 64 cols

    wmma::fragment<wmma::accumulator, 16, 16, 16, float> acc[2][4];
#pragma unroll
    for (int i = 0; i < 2; i++)
#pragma unroll
        for (int j = 0; j < 4; j++)
            wmma::load_matrix_sync(acc[i][j], sBias + wn * 64 + j * 16, BPAD,
                                   wmma::mem_row_major);

    const uint4* GBh = (const uint4*)g_wh;
    uint4 rbh[4];

    // B chunk: 32 k-rows x 256 n-cols fp16 = 1024 uint4; 4/thread.
#define LOADB(kc)                                                               \
    {                                                                           \
        _Pragma("unroll")                                                       \
        for (int u = 0; u < 4; u++) {                                           \
            int p = t + 256 * u;                                                \
            int row = p >> 5, c8 = p & 31;                                      \
            size_t gi = (size_t)((kc) + row) * 32 + c8;                         \
            rbh[u] = GBh[gi];                                                   \
        }                                                                       \
    }
#define STOREB()                                                                \
    {                                                                           \
        _Pragma("unroll")                                                       \
        for (int u = 0; u < 4; u++) {                                           \
            int p = t + 256 * u;                                                \
            int row = p >> 5, c8 = p & 31;                                      \
            *(uint4*)(sBh + row * BPAD + c8 * 8) = rbh[u];                      \
        }                                                                       \
    }

    LOADB(0);
#pragma unroll 1
    for (int c = 0; c < 8; c++) {
        __syncthreads();             // prior reads (incl. bias) done before overwrite
        STOREB();
        __syncthreads();
        if (c < 7) LOADB((c + 1) * 32);
        int kc = c * 32;

#pragma unroll
        for (int kk = 0; kk < 32; kk += 16) {
            wmma::fragment<wmma::matrix_a, 16, 16, 16, __half, wmma::row_major> fah[2], fal[2];
            wmma::fragment<wmma::matrix_b, 16, 16, 16, __half, wmma::row_major> fbh[4];
#pragma unroll
            for (int i = 0; i < 2; i++) {
                wmma::load_matrix_sync(fah[i], sAh + (wm * 32 + i * 16) * APAD + kc + kk, APAD);
                wmma::load_matrix_sync(fal[i], sAl + (wm * 32 + i * 16) * APAD + kc + kk, APAD);
            }
#pragma unroll
            for (int j = 0; j < 4; j++)
                wmma::load_matrix_sync(fbh[j], sBh + kk * BPAD + wn * 64 + j * 16, BPAD);
#pragma unroll
            for (int i = 0; i < 2; i++)
#pragma unroll
                for (int j = 0; j < 4; j++) {
                    wmma::mma_sync(acc[i][j], fal[i], fbh[j], acc[i][j]);
                    wmma::mma_sync(acc[i][j], fah[i], fbh[j], acc[i][j]);
                }
        }
    }

    // epilogue: fragments straight to global (bias already inside; M%16==0)
#pragma unroll
    for (int i = 0; i < 2; i++) {
        int gm = m0 + wm * 32 + i * 16;
        if (gm < N) {
#pragma unroll
            for (int j = 0; j < 4; j++)
                wmma::store_matrix_sync(out + (size_t)gm * D_OUT + wn * 64 + j * 16,
                                        acc[i][j], D_OUT, wmma::mem_row_major);
        }
    }
#undef LOADB
#undef STOREB
}

// ---------------- launch -----------------------------------------------------
extern "C" void kernel_launch(void* const* d_in, const int* in_sizes, int n_in,
                              void* d_out, int out_size) {
    const float* feat      = (const float*)d_in[0];
    const float* edge_feat = (const float*)d_in[1];
    const int*   src       = (const int*)d_in[2];
    const int*   dst       = (const int*)d_in[3];
    const float* weight    = (const float*)d_in[4];
    const float* bias      = (const float*)d_in[5];
    float* out = (float*)d_out;

    int N = in_sizes[0] / D_NODE;   // 50000
    int E = in_sizes[2];            // 800000

    zero_kernel<<<(N + 255) / 256, 256>>>(N);
    degree_kernel<<<(E + 255) / 256, 256>>>(src, dst, E);
    offsets_kernel<<<(N + 255) / 256, 256>>>(N);
    bucket_kernel<<<(E + 255) / 256, 256>>>(src, dst, E);
    fconv_kernel<<<(N * (D_NODE / 4) + 255) / 256, 256>>>(feat, N);
    wsplit_kernel<<<(D_IN * D_OUT + 255) / 256, 256>>>(weight);

    static int smem_set = 0;
    if (!smem_set) {
        cudaFuncSetAttribute(fused_kernel,
                             cudaFuncAttributeMaxDynamicSharedMemorySize, FUSED_SMEM);
        smem_set = 1;
    }
    fused_kernel<<<(N + 63) / 64, 256, FUSED_SMEM>>>(edge_feat, bias, out, N);
}